// round 2
// baseline (speedup 1.0000x reference)
#include <cuda_runtime.h>
#include <cstdint>

// Problem constants
#define NB_BITS   64
#define NB_GROUPS 8
#define PB        8            // bits per group
#define TBL       32768        // MAX_TABLE = 2^(P + N_GROUPS - 1)
#define BATCH     524288
#define TILE      256          // batch elements per block

// Transposed table: [g][addr][p] so the 8 p-values per (g,addr) are one
// contiguous, 32B-aligned entry (one L2 sector per gather).
__device__ float d_tpose[NB_GROUPS * TBL * 8];   // 8 MB scratch (device global, no alloc)

// -------------------------------------------------------------------------
// Kernel 1: transpose group_tables (8,8,32768) -> (8,32768,8)
// -------------------------------------------------------------------------
__global__ __launch_bounds__(256) void transpose_kernel(const float* __restrict__ gt) {
    int idx = blockIdx.x * blockDim.x + threadIdx.x;   // g*32768 + addr
    int g = idx >> 15;
    int a = idx & (TBL - 1);
    float v[8];
#pragma unroll
    for (int p = 0; p < 8; ++p)
        v[p] = __ldg(&gt[((g * 8 + p) << 15) + a]);    // coalesced across lanes (consecutive a)
    float4* dst = reinterpret_cast<float4*>(d_tpose) + ((size_t)idx << 1);
    dst[0] = make_float4(v[0], v[1], v[2], v[3]);
    dst[1] = make_float4(v[4], v[5], v[6], v[7]);
}

// -------------------------------------------------------------------------
// Kernel 2: main mapper. 256 threads / 256 batch elements per block.
// -------------------------------------------------------------------------
__global__ __launch_bounds__(256) void mapper_kernel(
    const int4*  __restrict__ bits4,    // bits as int4 (16 int4 per element)
    const int*   __restrict__ carry,    // (7, 256) int32 0/1
    float4*      __restrict__ out4)     // out as float4 (16 per element)
{
    __shared__ uint8_t  s_nib[TILE * 16];   // 4 KB: 16 nibbles (as bytes) per element
    __shared__ uint16_t s_addr[TILE * 8];   // 4 KB: 8 table addresses per element
    __shared__ uint8_t  s_carry[7 * 256];   // 1792 B carry tables (byte values)

    const int t = threadIdx.x;
    const size_t base4 = (size_t)blockIdx.x * (TILE * 16);   // int4/float4 tile base

    // Stage carry tables (tiny, coalesced)
    for (int i = t; i < 7 * 256; i += TILE)
        s_carry[i] = (uint8_t)carry[i];

    // ---- Phase A: coalesced bit loads, pack 4 bits -> nibble ----
#pragma unroll
    for (int i = 0; i < 16; ++i) {
        int L = i * TILE + t;                       // int4 index within tile
        int4 v = __ldcs(&bits4[base4 + L]);         // streaming: no L2 pollution
        s_nib[L] = (uint8_t)((v.x << 3) | (v.y << 2) | (v.z << 1) | v.w);
    }
    __syncthreads();

    // ---- Phase B: per-element address computation (one element per thread) ----
    {
        // 16 nibble-bytes, LDS.128 conflict-free
        uint4 nb = *reinterpret_cast<const uint4*>(&s_nib[t * 16]);
        uint32_t wv[4] = {nb.x, nb.y, nb.z, nb.w};

        uint32_t pk[4];
        uint32_t c_run = 0;
#pragma unroll
        for (int g = 0; g < 8; ++g) {
            uint32_t w  = wv[g >> 1];
            uint32_t sh = (g & 1) * 16;
            uint32_t hi = (w >> sh) & 0xFFu;          // nibble 2g   (bits p=0..3, MSB side)
            uint32_t lo = (w >> (sh + 8)) & 0xFFu;    // nibble 2g+1 (bits p=4..7)
            uint32_t ga = (hi << 4) | lo;             // 8-bit group address
            uint32_t addr = (g == 0) ? ga : ((ga << g) | c_run);
            if ((g & 1) == 0) pk[g >> 1] = addr;
            else              pk[g >> 1] |= (addr << 16);
            if (g < 7)
                c_run = (c_run << 1) | (uint32_t)s_carry[(g << 8) + ga];
        }
        // one STS.128, conflict-free
        *reinterpret_cast<uint4*>(&s_addr[t * 8]) = make_uint4(pk[0], pk[1], pk[2], pk[3]);
    }
    __syncthreads();

    // ---- Phase C: cooperative gather + perfectly coalesced output ----
    const float4* __restrict__ tp = reinterpret_cast<const float4*>(d_tpose);
#pragma unroll
    for (int i = 0; i < 16; ++i) {
        int L = i * TILE + t;          // output float4 index within tile
        int e = L >> 4;                // element in tile
        int g = (L >> 1) & 7;          // group
        int h = L & 1;                 // low/high half of 32B entry
        uint32_t addr = s_addr[(e << 3) + g];
        out4[base4 + L] = tp[((((uint32_t)g << 15) | addr) << 1) + h];
    }
}

// -------------------------------------------------------------------------
extern "C" void kernel_launch(void* const* d_in, const int* in_sizes, int n_in,
                              void* d_out, int out_size) {
    const int4*  bits4 = (const int4*)d_in[0];       // (B, 64) int32
    const float* gt    = (const float*)d_in[1];      // (8, 8, 32768) f32
    const int*   carry = (const int*)d_in[2];        // (7, 256) int32
    float4*      out4  = (float4*)d_out;             // (B, 64) f32

    (void)in_sizes; (void)n_in; (void)out_size;

    transpose_kernel<<<(NB_GROUPS * TBL) / 256, 256>>>(gt);
    mapper_kernel<<<BATCH / TILE, TILE>>>(bits4, carry, out4);
}

// round 3
// speedup vs baseline: 1.1176x; 1.1176x over previous
#include <cuda_runtime.h>
#include <cstdint>

#define NB_GROUPS 8
#define TBL       32768        // 2^(P + N_GROUPS - 1)
#define BATCH     524288

// Transposed table: [g][addr][p] -> each (g,addr) entry is one contiguous,
// 32B-aligned 8-float block (one L2 sector per gather).
__device__ float d_tpose[NB_GROUPS * TBL * 8];   // 8 MB device-global scratch

// -------------------------------------------------------------------------
// Kernel 1: transpose group_tables (8,8,32768) -> (8,32768,8)
// -------------------------------------------------------------------------
__global__ __launch_bounds__(256) void transpose_kernel(const float* __restrict__ gt) {
    int idx = blockIdx.x * blockDim.x + threadIdx.x;   // g*32768 + addr
    int g = idx >> 15;
    int a = idx & (TBL - 1);
    float v[8];
#pragma unroll
    for (int p = 0; p < 8; ++p)
        v[p] = __ldg(&gt[((g * 8 + p) << 15) + a]);    // coalesced across lanes
    float4* dst = reinterpret_cast<float4*>(d_tpose) + ((size_t)idx << 1);
    dst[0] = make_float4(v[0], v[1], v[2], v[3]);
    dst[1] = make_float4(v[4], v[5], v[6], v[7]);
}

// -------------------------------------------------------------------------
// Kernel 2: warp-autonomous mapper. Each warp owns 32 batch elements.
// No block barriers: ballot-based bit collection keeps everything in
// registers until the tiny per-warp address-redistribution via smem.
// -------------------------------------------------------------------------
__global__ __launch_bounds__(256, 8) void mapper_kernel(
    const int* __restrict__ bits,     // (B, 64) int32 0/1
    const int* __restrict__ carry,    // (7, 256) int32 0/1
    float4*    __restrict__ out4)     // out viewed as float4
{
    __shared__ uint8_t  s_carry[7 * 256];      // carry LUT (bytes)
    __shared__ uint16_t s_addr[8 * 32 * 8];    // [warp][elem][group] addresses

    const int t    = threadIdx.x;
    const int wid  = t >> 5;
    const int lane = t & 31;

    // Stage carry tables once (block-wide, single barrier for the whole kernel)
    for (int i = t; i < 7 * 256; i += 256)
        s_carry[i] = (uint8_t)carry[i];
    __syncthreads();

    const int warp_elem_base = (blockIdx.x * 8 + wid) * 32;   // 32 elems per warp
    const int* bp = bits + (size_t)warp_elem_base * 64;       // warp's 2048 ints

    // ---- Phase 1: ballot-collapse 2048 ints -> 32x (w0,w1) 64-bit patterns ----
    uint32_t w0 = 0, w1 = 0;
#pragma unroll
    for (int jb = 0; jb < 8; ++jb) {
        uint32_t v[8];
#pragma unroll
        for (int u = 0; u < 8; ++u)
            v[u] = (uint32_t)__ldcs(&bp[(jb * 8 + u) * 32 + lane]);   // coalesced 128B
#pragma unroll
        for (int u = 0; u < 8; ++u) {
            int j = jb * 8 + u;                         // 32-int chunk index
            uint32_t b = __ballot_sync(0xFFFFFFFFu, v[u] != 0);
            // chunk j holds bits [32j, 32j+32) of the flat stream:
            // element j>>1, half j&1. Owner lane keeps it.
            if (lane == (j >> 1)) { if (j & 1) w1 = b; else w0 = b; }
        }
    }

    // ---- Phase 2: per-lane group addresses + carry chain (element = lane) ----
    {
        // ballot bit k == element bit k; group byte g needs MSB-first weights,
        // i.e. the bit-reversed byte.
        uint32_t r0 = __brev(w0);
        uint32_t r1 = __brev(w1);
        uint32_t ga[8];
#pragma unroll
        for (int g = 0; g < 4; ++g) ga[g]     = (r0 >> (24 - 8 * g)) & 0xFFu;
#pragma unroll
        for (int g = 0; g < 4; ++g) ga[4 + g] = (r1 >> (24 - 8 * g)) & 0xFFu;

        uint32_t pk[4];
        uint32_t c_run = 0;
#pragma unroll
        for (int g = 0; g < 8; ++g) {
            uint32_t addr = (g == 0) ? ga[0] : ((ga[g] << g) | c_run);
            if ((g & 1) == 0) pk[g >> 1] = addr;
            else              pk[g >> 1] |= (addr << 16);
            if (g < 7)
                c_run = (c_run << 1) | (uint32_t)s_carry[(g << 8) + ga[g]];
        }
        // one STS.128 into this warp's region
        *reinterpret_cast<uint4*>(&s_addr[(wid << 8) + (lane << 3)]) =
            make_uint4(pk[0], pk[1], pk[2], pk[3]);
    }
    __syncwarp();

    // ---- Phase 3: cooperative gather + perfectly coalesced streaming stores ----
    const float4* __restrict__ tp = reinterpret_cast<const float4*>(d_tpose);
    const uint16_t* __restrict__ sa = &s_addr[wid << 8];
    float4* __restrict__ ob = out4 + (size_t)warp_elem_base * 16;
#pragma unroll
    for (int i = 0; i < 16; ++i) {
        int L = i * 32 + lane;            // output float4 index within warp tile
        int e = L >> 4;                   // element within warp (0..31)
        int g = (L >> 1) & 7;             // group
        int h = L & 1;                    // low/high half of the 32B entry
        uint32_t addr = sa[(e << 3) + g];
        float4 val = tp[((uint32_t)g << 16) | (addr << 1) | (uint32_t)h];
        __stcs(&ob[L], val);              // evict-first: keep table in L2
    }
}

// -------------------------------------------------------------------------
extern "C" void kernel_launch(void* const* d_in, const int* in_sizes, int n_in,
                              void* d_out, int out_size) {
    const int*   b     = (const int*)d_in[0];        // (B, 64) int32
    const float* gt    = (const float*)d_in[1];      // (8, 8, 32768) f32
    const int*   carry = (const int*)d_in[2];        // (7, 256) int32
    float4*      out4  = (float4*)d_out;             // (B, 64) f32

    (void)in_sizes; (void)n_in; (void)out_size;

    transpose_kernel<<<(NB_GROUPS * TBL) / 256, 256>>>(gt);
    mapper_kernel<<<BATCH / 256, 256>>>(b, carry, out4);
}

// round 4
// speedup vs baseline: 1.1990x; 1.0728x over previous
#include <cuda_runtime.h>
#include <cstdint>

#define NB_GROUPS 8
#define TBL       32768          // 2^(P + N_GROUPS - 1)
#define BATCH     524288
#define N_TILES   (BATCH / 32)   // 16384 warp-tiles of 32 elements
#define GRID_MAP  (148 * 6)      // all-resident persistent grid

// Transposed table: [g][addr][p] -> each (g,addr) entry is one contiguous,
// 32B-aligned 8-float block (one L2 sector per gather).
__device__ float d_tpose[NB_GROUPS * TBL * 8];   // 8 MB device-global scratch
__device__ unsigned int d_ticket;                // warp-tile work counter

// -------------------------------------------------------------------------
// Kernel 1: transpose group_tables (8,8,32768) -> (8,32768,8); reset ticket.
// -------------------------------------------------------------------------
__global__ __launch_bounds__(256) void transpose_kernel(const float* __restrict__ gt) {
    int idx = blockIdx.x * blockDim.x + threadIdx.x;   // g*32768 + addr
    if (idx == 0) d_ticket = 0;                        // runs before mapper on-stream
    int g = idx >> 15;
    int a = idx & (TBL - 1);
    float v[8];
#pragma unroll
    for (int p = 0; p < 8; ++p)
        v[p] = __ldg(&gt[((g * 8 + p) << 15) + a]);    // coalesced across lanes
    float4* dst = reinterpret_cast<float4*>(d_tpose) + ((size_t)idx << 1);
    dst[0] = make_float4(v[0], v[1], v[2], v[3]);
    dst[1] = make_float4(v[4], v[5], v[6], v[7]);
}

// -------------------------------------------------------------------------
// Kernel 2: persistent warp-autonomous mapper with atomic ticketing.
// Each warp pulls 32-element tiles until work is exhausted.
// -------------------------------------------------------------------------
__global__ __launch_bounds__(256, 6) void mapper_kernel(
    const int4* __restrict__ bits4,   // (B, 64) int32 viewed as int4
    const int*  __restrict__ carry,   // (7, 256) int32 0/1
    float4*     __restrict__ out4)    // out viewed as float4
{
    __shared__ uint8_t  s_nib[8][512];      // [warp][int4-slot] nibble bytes
    __shared__ uint16_t s_addr[8][256];     // [warp][elem*8+g] table addresses
    __shared__ uint8_t  s_carry[7 * 256];   // carry LUT (bytes)

    const int t    = threadIdx.x;
    const int wid  = t >> 5;
    const int lane = t & 31;

    for (int i = t; i < 7 * 256; i += 256)
        s_carry[i] = (uint8_t)carry[i];
    __syncthreads();

    const float4* __restrict__ tp = reinterpret_cast<const float4*>(d_tpose);

    for (;;) {
        // ---- pull next warp-tile ----
        unsigned int tile;
        if (lane == 0) tile = atomicAdd(&d_ticket, 1u);
        tile = __shfl_sync(0xFFFFFFFFu, tile, 0);
        if (tile >= N_TILES) break;

        const int4* bp4 = bits4 + (size_t)tile * 512;   // 32 elems * 16 int4

        // ---- Phase A: 16 coalesced int4 loads -> nibble bytes in smem ----
#pragma unroll
        for (int i = 0; i < 16; ++i) {
            int L = i * 32 + lane;
            int4 v = __ldcs(&bp4[L]);
            s_nib[wid][L] = (uint8_t)((v.x << 3) | (v.y << 2) | (v.z << 1) | v.w);
        }
        __syncwarp();

        // ---- Phase B: per-lane (element = lane) addresses + carry chain ----
        {
            uint4 nb = *reinterpret_cast<const uint4*>(&s_nib[wid][lane * 16]);
            uint32_t wv[4] = {nb.x, nb.y, nb.z, nb.w};

            uint32_t pk[4];
            uint32_t c_run = 0;
#pragma unroll
            for (int g = 0; g < 8; ++g) {
                uint32_t w  = wv[g >> 1];
                uint32_t sh = (g & 1) * 16;
                uint32_t hi = (w >> sh) & 0xFFu;        // nibble 2g   (p=0..3)
                uint32_t lo = (w >> (sh + 8)) & 0xFFu;  // nibble 2g+1 (p=4..7)
                uint32_t ga = (hi << 4) | lo;
                uint32_t addr = (g == 0) ? ga : ((ga << g) | c_run);
                if ((g & 1) == 0) pk[g >> 1] = addr;
                else              pk[g >> 1] |= (addr << 16);
                if (g < 7)
                    c_run = (c_run << 1) | (uint32_t)s_carry[(g << 8) + ga];
            }
            *reinterpret_cast<uint4*>(&s_addr[wid][lane * 8]) =
                make_uint4(pk[0], pk[1], pk[2], pk[3]);
        }
        __syncwarp();

        // ---- Phase C: cooperative gather + coalesced streaming stores ----
        float4* __restrict__ ob = out4 + (size_t)tile * 512;
#pragma unroll
        for (int i = 0; i < 16; ++i) {
            int L = i * 32 + lane;            // output float4 index within tile
            int e = L >> 4;                   // element within tile
            int g = (L >> 1) & 7;             // group
            int h = L & 1;                    // half of the 32B entry
            uint32_t addr = s_addr[wid][(e << 3) + g];
            float4 val = __ldg(&tp[((uint32_t)g << 16) | (addr << 1) | (uint32_t)h]);
            __stcs(&ob[L], val);              // evict-first: keep table in L2
        }
        __syncwarp();   // protect s_addr/s_nib against next-iteration overwrite
    }
}

// -------------------------------------------------------------------------
extern "C" void kernel_launch(void* const* d_in, const int* in_sizes, int n_in,
                              void* d_out, int out_size) {
    const int4*  bits4 = (const int4*)d_in[0];       // (B, 64) int32
    const float* gt    = (const float*)d_in[1];      // (8, 8, 32768) f32
    const int*   carry = (const int*)d_in[2];        // (7, 256) int32
    float4*      out4  = (float4*)d_out;             // (B, 64) f32

    (void)in_sizes; (void)n_in; (void)out_size;

    transpose_kernel<<<(NB_GROUPS * TBL) / 256, 256>>>(gt);
    mapper_kernel<<<GRID_MAP, 256>>>(bits4, carry, out4);
}